// round 4
// baseline (speedup 1.0000x reference)
#include <cuda_runtime.h>
#include <cuda_bf16.h>
#include <cstdint>
#include <math.h>

#define NLAYERS 4
#define NQ      256
#define DIM     1024
#define MGAL    51200
#define KC      64                 // k-chunk (int8 elems)
#define NCHUNK  (DIM / KC)         // 16
#define TILE_G  128                // gallery rows per CTA
#define NTILES  (MGAL / TILE_G)    // 400

#define ROWB    80                 // 64B data + 16B pad (conflict-free ldmatrix)
#define ST_A    (NQ * ROWB)        // 20480
#define ST_B    (TILE_G * ROWB)    // 10240
#define STAGE   (ST_A + ST_B)      // 30720
#define OFF_INVN (2 * STAGE)       // 61440 (128 floats)
#define OFF_FQ   (OFF_INVN + 512)  // 61952 (256 floats)
#define SMEM_BYTES (OFF_FQ + 1024) // 62976

#define GSCALE  (127.0f / 6.0f)    // global gallery int8 scale (data ~ N(0,1))
#define GINV    (6.0f / 127.0f)

__device__ uint32_t g_qi8[NLAYERS * NQ * DIM / 4];  // packed int8 queries (normalized+scaled)
__device__ float    g_fq[NLAYERS * NQ];             // per-query dequant factor
__device__ unsigned int g_simmax[NLAYERS * NQ];     // monotone-encoded float max

// ---------------- helpers ----------------
__device__ __forceinline__ uint32_t smem_u32(const void* p) {
    uint32_t a;
    asm("{ .reg .u64 t; cvta.to.shared.u64 t, %1; cvt.u32.u64 %0, t; }" : "=r"(a) : "l"(p));
    return a;
}
__device__ __forceinline__ unsigned enc_f(float f) {
    unsigned u = __float_as_uint(f);
    return (u & 0x80000000u) ? ~u : (u | 0x80000000u);
}
__device__ __forceinline__ float dec_f(unsigned u) {
    return __uint_as_float((u & 0x80000000u) ? (u & 0x7fffffffu) : ~u);
}
// pack 4 floats (pre-scaled) -> 4 saturated int8 in one b32 (byte0 = v0)
__device__ __forceinline__ uint32_t quant4(float a, float b, float c, float d) {
    int v0 = __float2int_rn(a), v1 = __float2int_rn(b);
    int v2 = __float2int_rn(c), v3 = __float2int_rn(d);
    uint32_t t, r;
    asm("cvt.pack.sat.s8.s32.b32 %0, %1, %2, %3;" : "=r"(t) : "r"(v3), "r"(v2), "r"(0));
    asm("cvt.pack.sat.s8.s32.b32 %0, %1, %2, %3;" : "=r"(r) : "r"(v1), "r"(v0), "r"(t));
    return r;
}
__device__ __forceinline__ void mma_s8(int* d, const uint32_t* a, uint32_t b0, uint32_t b1) {
    asm volatile(
        "mma.sync.aligned.m16n8k32.row.col.s32.s8.s8.s32 "
        "{%0,%1,%2,%3}, {%4,%5,%6,%7}, {%8,%9}, {%0,%1,%2,%3};"
        : "+r"(d[0]), "+r"(d[1]), "+r"(d[2]), "+r"(d[3])
        : "r"(a[0]), "r"(a[1]), "r"(a[2]), "r"(a[3]), "r"(b0), "r"(b1));
}
__device__ __forceinline__ void ldmx4(uint32_t* r, uint32_t addr) {
    asm volatile("ldmatrix.sync.aligned.m8n8.x4.shared.b16 {%0,%1,%2,%3}, [%4];"
                 : "=r"(r[0]), "=r"(r[1]), "=r"(r[2]), "=r"(r[3]) : "r"(addr));
}

// ---------------- small kernels ----------------
__global__ void init_kernel() {
    int i = blockIdx.x * blockDim.x + threadIdx.x;
    if (i < NLAYERS * NQ) g_simmax[i] = 0x007FFFFFu;  // enc(-inf)
}

// normalize queries, per-row int8 quantization. One block per (l,n) row.
__global__ void prep_q_kernel(const float* __restrict__ q) {
    int row = blockIdx.x;                      // l*NQ + n
    const float4 f = reinterpret_cast<const float4*>(q + (size_t)row * DIM)[threadIdx.x];
    __shared__ float red[8];
    // pass 1: sum of squares
    float ss = f.x*f.x + f.y*f.y + f.z*f.z + f.w*f.w;
    #pragma unroll
    for (int o = 16; o; o >>= 1) ss += __shfl_xor_sync(~0u, ss, o);
    if ((threadIdx.x & 31) == 0) red[threadIdx.x >> 5] = ss;
    __syncthreads();
    if (threadIdx.x < 8) {
        float s = red[threadIdx.x];
        #pragma unroll
        for (int o = 4; o; o >>= 1) s += __shfl_xor_sync(0xffu, s, o);
        if (threadIdx.x == 0) red[0] = s;
    }
    __syncthreads();
    float inv = 1.0f / fmaxf(sqrtf(red[0]), 1e-8f);
    float vx = f.x * inv, vy = f.y * inv, vz = f.z * inv, vw = f.w * inv;
    __syncthreads();
    // pass 2: row max-abs of normalized values
    float m = fmaxf(fmaxf(fabsf(vx), fabsf(vy)), fmaxf(fabsf(vz), fabsf(vw)));
    #pragma unroll
    for (int o = 16; o; o >>= 1) m = fmaxf(m, __shfl_xor_sync(~0u, m, o));
    if ((threadIdx.x & 31) == 0) red[threadIdx.x >> 5] = m;
    __syncthreads();
    if (threadIdx.x < 8) {
        float s = red[threadIdx.x];
        #pragma unroll
        for (int o = 4; o; o >>= 1) s = fmaxf(s, __shfl_xor_sync(0xffu, s, o));
        if (threadIdx.x == 0) red[0] = s;
    }
    __syncthreads();
    float mx = fmaxf(red[0], 1e-20f);
    float s = 127.0f / mx;
    g_qi8[(size_t)row * 256 + threadIdx.x] = quant4(vx * s, vy * s, vz * s, vw * s);
    if (threadIdx.x == 0) g_fq[row] = mx * (1.0f / 127.0f);
}

__global__ void finalize_kernel(float* __restrict__ out) {
    int n = threadIdx.x;
    float s = 0.0f;
    #pragma unroll
    for (int l = 0; l < NLAYERS; l++) s += dec_f(g_simmax[l * NQ + n]);
    out[n] = 1.0f - s * (1.0f / NLAYERS);
}

// ---------------- main int8 GEMM + max kernel ----------------
__global__ __launch_bounds__(256, 1)
void gemm_max_kernel(const float* __restrict__ gal) {
    extern __shared__ char smem[];
    const uint32_t sb = smem_u32(smem);
    const int tid = threadIdx.x, wid = tid >> 5, lid = tid & 31;
    const int l  = blockIdx.y;
    const int g0 = blockIdx.x * TILE_G;
    const float*    gB = gal + ((size_t)l * MGAL + g0) * DIM;
    const uint32_t* gA = g_qi8 + (size_t)l * NQ * 256;

    float* invn  = reinterpret_cast<float*>(smem + OFF_INVN);
    float* fqArr = reinterpret_cast<float*>(smem + OFF_FQ);
    fqArr[tid] = g_fq[l * NQ + tid];

    const int brow = tid >> 1, bhalf = tid & 1;     // B staging: row / 32-col half
    const int wm = wid >> 1, wn = wid & 1;          // warp tile: 64 q-rows x 64 g-rows

    int acc[4][8][4];
    #pragma unroll
    for (int mt = 0; mt < 4; mt++)
        #pragma unroll
        for (int nt = 0; nt < 8; nt++)
            #pragma unroll
            for (int e = 0; e < 4; e++) acc[mt][nt][e] = 0;

    float4 pb[8];
    float ss = 0.0f;

    // ---- prologue: B chunk0 -> regs, A chunk0 -> smem stage0 ----
    {
        const float* src = gB + (size_t)brow * DIM + bhalf * 32;
        #pragma unroll
        for (int i = 0; i < 8; i++) pb[i] = *reinterpret_cast<const float4*>(src + i * 4);
        const uint32_t* asrc = gA + (size_t)tid * 256;
        #pragma unroll
        for (int u = 0; u < 4; u++) {
            uint32_t dst = sb + (uint32_t)(tid * ROWB + u * 16);
            asm volatile("cp.async.ca.shared.global [%0], [%1], 16;"
                         :: "r"(dst), "l"(asrc + u * 4) : "memory");
        }
        asm volatile("cp.async.commit_group;" ::: "memory");
    }

    for (int c = 0; c < NCHUNK; c++) {
        const uint32_t bufb = sb + (uint32_t)(c & 1) * STAGE;

        // ---- quantize + store B (fp32 -> s8), accumulate raw sumsq ----
        {
            uint32_t w[8];
            #pragma unroll
            for (int i = 0; i < 8; i++) {
                float4 f = pb[i];
                ss = fmaf(f.x, f.x, fmaf(f.y, f.y, fmaf(f.z, f.z, fmaf(f.w, f.w, ss))));
                w[i] = quant4(f.x * GSCALE, f.y * GSCALE, f.z * GSCALE, f.w * GSCALE);
            }
            uint32_t dst = bufb + ST_A + (uint32_t)(brow * ROWB + bhalf * 32);
            asm volatile("st.shared.v4.b32 [%0], {%1, %2, %3, %4};"
                         :: "r"(dst), "r"(w[0]), "r"(w[1]), "r"(w[2]), "r"(w[3]) : "memory");
            asm volatile("st.shared.v4.b32 [%0], {%1, %2, %3, %4};"
                         :: "r"(dst + 16), "r"(w[4]), "r"(w[5]), "r"(w[6]), "r"(w[7]) : "memory");
        }

        // ---- A cp.async for next chunk into other stage ----
        if (c < NCHUNK - 1) {
            const uint32_t* asrc = gA + (size_t)tid * 256 + (c + 1) * 16;
            const uint32_t nbuf = sb + (uint32_t)((c + 1) & 1) * STAGE;
            #pragma unroll
            for (int u = 0; u < 4; u++) {
                uint32_t dst = nbuf + (uint32_t)(tid * ROWB + u * 16);
                asm volatile("cp.async.ca.shared.global [%0], [%1], 16;"
                             :: "r"(dst), "l"(asrc + u * 4) : "memory");
            }
            asm volatile("cp.async.commit_group;" ::: "memory");
            asm volatile("cp.async.wait_group 1;" ::: "memory");
        } else {
            asm volatile("cp.async.wait_group 0;" ::: "memory");
        }
        __syncthreads();

        // ---- prefetch next B chunk into regs (overlaps compute) ----
        if (c < NCHUNK - 1) {
            const float* src = gB + (size_t)brow * DIM + (c + 1) * KC + bhalf * 32;
            #pragma unroll
            for (int i = 0; i < 8; i++) pb[i] = *reinterpret_cast<const float4*>(src + i * 4);
        }

        // ---- compute: 2 k32-steps ----
        const uint32_t aBase = bufb;
        const uint32_t bBase = bufb + ST_A;
        const int rsel = lid & 15, usel = lid >> 4;
        #pragma unroll
        for (int ks = 0; ks < 2; ks++) {
            uint32_t afr[4][4], bfr[4][4];
            #pragma unroll
            for (int mt = 0; mt < 4; mt++)
                ldmx4(afr[mt], aBase + (uint32_t)((wm * 64 + mt * 16 + rsel) * ROWB + ks * 32 + usel * 16));
            #pragma unroll
            for (int g = 0; g < 4; g++)
                ldmx4(bfr[g], bBase + (uint32_t)((wn * 64 + g * 16 + rsel) * ROWB + ks * 32 + usel * 16));
            #pragma unroll
            for (int mt = 0; mt < 4; mt++)
                #pragma unroll
                for (int g = 0; g < 4; g++) {
                    mma_s8(acc[mt][2 * g],     afr[mt], bfr[g][0], bfr[g][2]);
                    mma_s8(acc[mt][2 * g + 1], afr[mt], bfr[g][1], bfr[g][3]);
                }
        }
        __syncthreads();
    }

    // ---- gallery inverse norms (fold in global int8 scale) ----
    ss += __shfl_xor_sync(~0u, ss, 1);
    if (bhalf == 0)
        invn[brow] = GINV / fmaxf(sqrtf(ss), 1e-8f);
    __syncthreads();

    // ---- epilogue: dequant, per-query max, global atomicMax ----
    #pragma unroll
    for (int mt = 0; mt < 4; mt++) {
        float mx0 = -INFINITY, mx1 = -INFINITY;
        #pragma unroll
        for (int nt = 0; nt < 8; nt++) {
            int colb = wn * 64 + nt * 8 + (lid & 3) * 2;
            float i0 = invn[colb], i1 = invn[colb + 1];
            mx0 = fmaxf(mx0, fmaxf(__int2float_rn(acc[mt][nt][0]) * i0,
                                   __int2float_rn(acc[mt][nt][1]) * i1));
            mx1 = fmaxf(mx1, fmaxf(__int2float_rn(acc[mt][nt][2]) * i0,
                                   __int2float_rn(acc[mt][nt][3]) * i1));
        }
        #pragma unroll
        for (int o = 1; o <= 2; o <<= 1) {
            mx0 = fmaxf(mx0, __shfl_xor_sync(~0u, mx0, o));
            mx1 = fmaxf(mx1, __shfl_xor_sync(~0u, mx1, o));
        }
        if ((lid & 3) == 0) {
            int r = wm * 64 + mt * 16 + (lid >> 2);
            atomicMax(&g_simmax[l * NQ + r],     enc_f(mx0 * fqArr[r]));
            atomicMax(&g_simmax[l * NQ + r + 8], enc_f(mx1 * fqArr[r + 8]));
        }
    }
}

// ---------------- launch ----------------
extern "C" void kernel_launch(void* const* d_in, const int* in_sizes, int n_in,
                              void* d_out, int out_size) {
    const float* q = (const float*)d_in[0];
    const float* g = (const float*)d_in[1];
    if (n_in >= 2 && in_sizes[0] > in_sizes[1]) {
        const float* t = q; q = g; g = t;
    }
    cudaFuncSetAttribute(gemm_max_kernel,
                         cudaFuncAttributeMaxDynamicSharedMemorySize, SMEM_BYTES);

    init_kernel<<<1, NLAYERS * NQ>>>();
    prep_q_kernel<<<NLAYERS * NQ, 256>>>(q);
    gemm_max_kernel<<<dim3(NTILES, NLAYERS), 256, SMEM_BYTES>>>(g);
    finalize_kernel<<<1, NQ>>>((float*)d_out);
}

// round 5
// speedup vs baseline: 1.4050x; 1.4050x over previous
#include <cuda_runtime.h>
#include <cuda_bf16.h>
#include <cstdint>
#include <math.h>

#define NLAYERS 4
#define NQ      256
#define DIM     1024
#define MGAL    51200
#define KC      64                 // k-chunk (fp8 elems)
#define NCHUNK  (DIM / KC)         // 16
#define TILE_G  128                // gallery rows per CTA
#define NTILES  (MGAL / TILE_G)    // 400

#define ROWB    80                 // 64B data + 16B pad (conflict-free ldmatrix)
#define ST_A    (NQ * ROWB)        // 20480
#define ST_B    (TILE_G * ROWB)    // 10240
#define STAGE   (ST_A + ST_B)      // 30720
#define OFF_INVN (2 * STAGE)       // 61440 (128 floats)
#define SMEM_BYTES (OFF_INVN + 512)

#define QSCALE  16.0f              // query pre-quant scale (into e4m3 normal range)
#define QINV    (1.0f / 16.0f)

__device__ uint32_t g_qf8[NLAYERS * NQ * DIM / 4];  // packed e4m3 queries (normalized*16)
__device__ unsigned int g_simmax[NLAYERS * NQ];     // monotone-encoded float max

// ---------------- helpers ----------------
__device__ __forceinline__ uint32_t smem_u32(const void* p) {
    uint32_t a;
    asm("{ .reg .u64 t; cvta.to.shared.u64 t, %1; cvt.u32.u64 %0, t; }" : "=r"(a) : "l"(p));
    return a;
}
__device__ __forceinline__ unsigned enc_f(float f) {
    unsigned u = __float_as_uint(f);
    return (u & 0x80000000u) ? ~u : (u | 0x80000000u);
}
__device__ __forceinline__ float dec_f(unsigned u) {
    return __uint_as_float((u & 0x80000000u) ? (u & 0x7fffffffu) : ~u);
}
// pack 4 floats -> 4 e4m3 bytes in one b32 (byte0 = a)
__device__ __forceinline__ uint32_t quant4_e4m3(float a, float b, float c, float d) {
    uint16_t lo, hi;
    asm("cvt.rn.satfinite.e4m3x2.f32 %0, %1, %2;" : "=h"(lo) : "f"(b), "f"(a));
    asm("cvt.rn.satfinite.e4m3x2.f32 %0, %1, %2;" : "=h"(hi) : "f"(d), "f"(c));
    return (uint32_t)lo | ((uint32_t)hi << 16);
}
__device__ __forceinline__ void mma_f8(float* d, const uint32_t* a, uint32_t b0, uint32_t b1) {
    asm volatile(
        "mma.sync.aligned.m16n8k32.row.col.f32.e4m3.e4m3.f32 "
        "{%0,%1,%2,%3}, {%4,%5,%6,%7}, {%8,%9}, {%0,%1,%2,%3};"
        : "+f"(d[0]), "+f"(d[1]), "+f"(d[2]), "+f"(d[3])
        : "r"(a[0]), "r"(a[1]), "r"(a[2]), "r"(a[3]), "r"(b0), "r"(b1));
}
__device__ __forceinline__ void ldmx4(uint32_t* r, uint32_t addr) {
    asm volatile("ldmatrix.sync.aligned.m8n8.x4.shared.b16 {%0,%1,%2,%3}, [%4];"
                 : "=r"(r[0]), "=r"(r[1]), "=r"(r[2]), "=r"(r[3]) : "r"(addr));
}

// ---------------- small kernels ----------------
__global__ void init_kernel() {
    int i = blockIdx.x * blockDim.x + threadIdx.x;
    if (i < NLAYERS * NQ) g_simmax[i] = 0x007FFFFFu;  // enc(-inf)
}

// normalize queries, scale by 16, e4m3 quantize. One block per (l,n) row.
__global__ void prep_q_kernel(const float* __restrict__ q) {
    int row = blockIdx.x;                      // l*NQ + n
    const float4 f = reinterpret_cast<const float4*>(q + (size_t)row * DIM)[threadIdx.x];
    __shared__ float red[8];
    float ss = f.x*f.x + f.y*f.y + f.z*f.z + f.w*f.w;
    #pragma unroll
    for (int o = 16; o; o >>= 1) ss += __shfl_xor_sync(~0u, ss, o);
    if ((threadIdx.x & 31) == 0) red[threadIdx.x >> 5] = ss;
    __syncthreads();
    if (threadIdx.x < 8) {
        float s = red[threadIdx.x];
        #pragma unroll
        for (int o = 4; o; o >>= 1) s += __shfl_xor_sync(0xffu, s, o);
        if (threadIdx.x == 0) red[0] = s;
    }
    __syncthreads();
    float inv = QSCALE / fmaxf(sqrtf(red[0]), 1e-8f);
    g_qf8[(size_t)row * 256 + threadIdx.x] =
        quant4_e4m3(f.x * inv, f.y * inv, f.z * inv, f.w * inv);
}

__global__ void finalize_kernel(float* __restrict__ out) {
    int n = threadIdx.x;
    float s = 0.0f;
    #pragma unroll
    for (int l = 0; l < NLAYERS; l++) s += dec_f(g_simmax[l * NQ + n]);
    out[n] = 1.0f - s * (1.0f / NLAYERS);
}

// ---------------- main fp8 GEMM + max kernel ----------------
__global__ __launch_bounds__(256, 1)
void gemm_max_kernel(const float* __restrict__ gal) {
    extern __shared__ char smem[];
    const uint32_t sb = smem_u32(smem);
    const int tid = threadIdx.x, wid = tid >> 5, lid = tid & 31;
    const int l  = blockIdx.y;
    const int g0 = blockIdx.x * TILE_G;
    const float*    gB = gal + ((size_t)l * MGAL + g0) * DIM;
    const uint32_t* gA = g_qf8 + (size_t)l * NQ * 256;

    float* invn = reinterpret_cast<float*>(smem + OFF_INVN);

    const int brow = tid >> 1, bhalf = tid & 1;     // B staging: row / 32-col half
    const int wm = wid >> 1, wn = wid & 1;          // warp tile: 64 q-rows x 64 g-rows

    float acc[4][8][4];
    #pragma unroll
    for (int mt = 0; mt < 4; mt++)
        #pragma unroll
        for (int nt = 0; nt < 8; nt++)
            #pragma unroll
            for (int e = 0; e < 4; e++) acc[mt][nt][e] = 0.0f;

    float4 pb[8];
    float ss = 0.0f;

    // ---- prologue: B chunk0 -> regs, A chunk0 -> smem stage0 ----
    {
        const float* src = gB + (size_t)brow * DIM + bhalf * 32;
        #pragma unroll
        for (int i = 0; i < 8; i++) pb[i] = *reinterpret_cast<const float4*>(src + i * 4);
        const uint32_t* asrc = gA + (size_t)tid * 256;
        #pragma unroll
        for (int u = 0; u < 4; u++) {
            uint32_t dst = sb + (uint32_t)(tid * ROWB + u * 16);
            asm volatile("cp.async.ca.shared.global [%0], [%1], 16;"
                         :: "r"(dst), "l"(asrc + u * 4) : "memory");
        }
        asm volatile("cp.async.commit_group;" ::: "memory");
    }

    for (int c = 0; c < NCHUNK; c++) {
        const uint32_t bufb = sb + (uint32_t)(c & 1) * STAGE;

        // ---- convert + store B (fp32 -> e4m3), accumulate raw sumsq ----
        {
            uint32_t w[8];
            #pragma unroll
            for (int i = 0; i < 8; i++) {
                float4 f = pb[i];
                ss = fmaf(f.x, f.x, fmaf(f.y, f.y, fmaf(f.z, f.z, fmaf(f.w, f.w, ss))));
                w[i] = quant4_e4m3(f.x, f.y, f.z, f.w);
            }
            uint32_t dst = bufb + ST_A + (uint32_t)(brow * ROWB + bhalf * 32);
            asm volatile("st.shared.v4.b32 [%0], {%1, %2, %3, %4};"
                         :: "r"(dst), "r"(w[0]), "r"(w[1]), "r"(w[2]), "r"(w[3]) : "memory");
            asm volatile("st.shared.v4.b32 [%0], {%1, %2, %3, %4};"
                         :: "r"(dst + 16), "r"(w[4]), "r"(w[5]), "r"(w[6]), "r"(w[7]) : "memory");
        }

        // ---- A cp.async for next chunk into other stage ----
        if (c < NCHUNK - 1) {
            const uint32_t* asrc = gA + (size_t)tid * 256 + (c + 1) * 16;
            const uint32_t nbuf = sb + (uint32_t)((c + 1) & 1) * STAGE;
            #pragma unroll
            for (int u = 0; u < 4; u++) {
                uint32_t dst = nbuf + (uint32_t)(tid * ROWB + u * 16);
                asm volatile("cp.async.ca.shared.global [%0], [%1], 16;"
                             :: "r"(dst), "l"(asrc + u * 4) : "memory");
            }
            asm volatile("cp.async.commit_group;" ::: "memory");
            asm volatile("cp.async.wait_group 1;" ::: "memory");
        } else {
            asm volatile("cp.async.wait_group 0;" ::: "memory");
        }
        __syncthreads();

        // ---- prefetch next B chunk into regs (overlaps compute) ----
        if (c < NCHUNK - 1) {
            const float* src = gB + (size_t)brow * DIM + (c + 1) * KC + bhalf * 32;
            #pragma unroll
            for (int i = 0; i < 8; i++) pb[i] = *reinterpret_cast<const float4*>(src + i * 4);
        }

        // ---- compute: 2 k32-steps ----
        const uint32_t aBase = bufb;
        const uint32_t bBase = bufb + ST_A;
        const int rsel = lid & 15, usel = lid >> 4;
        #pragma unroll
        for (int ks = 0; ks < 2; ks++) {
            uint32_t afr[4][4], bfr[4][4];
            #pragma unroll
            for (int mt = 0; mt < 4; mt++)
                ldmx4(afr[mt], aBase + (uint32_t)((wm * 64 + mt * 16 + rsel) * ROWB + ks * 32 + usel * 16));
            #pragma unroll
            for (int g = 0; g < 4; g++)
                ldmx4(bfr[g], bBase + (uint32_t)((wn * 64 + g * 16 + rsel) * ROWB + ks * 32 + usel * 16));
            #pragma unroll
            for (int mt = 0; mt < 4; mt++)
                #pragma unroll
                for (int g = 0; g < 4; g++) {
                    mma_f8(acc[mt][2 * g],     afr[mt], bfr[g][0], bfr[g][2]);
                    mma_f8(acc[mt][2 * g + 1], afr[mt], bfr[g][1], bfr[g][3]);
                }
        }
        __syncthreads();
    }

    // ---- gallery inverse norms (fold query 1/16 scale in) ----
    ss += __shfl_xor_sync(~0u, ss, 1);
    if (bhalf == 0)
        invn[brow] = QINV / fmaxf(sqrtf(ss), 1e-8f);
    __syncthreads();

    // ---- epilogue: scale, per-query max, global atomicMax ----
    #pragma unroll
    for (int mt = 0; mt < 4; mt++) {
        float mx0 = -INFINITY, mx1 = -INFINITY;
        #pragma unroll
        for (int nt = 0; nt < 8; nt++) {
            int colb = wn * 64 + nt * 8 + (lid & 3) * 2;
            float i0 = invn[colb], i1 = invn[colb + 1];
            mx0 = fmaxf(mx0, fmaxf(acc[mt][nt][0] * i0, acc[mt][nt][1] * i1));
            mx1 = fmaxf(mx1, fmaxf(acc[mt][nt][2] * i0, acc[mt][nt][3] * i1));
        }
        #pragma unroll
        for (int o = 1; o <= 2; o <<= 1) {
            mx0 = fmaxf(mx0, __shfl_xor_sync(~0u, mx0, o));
            mx1 = fmaxf(mx1, __shfl_xor_sync(~0u, mx1, o));
        }
        if ((lid & 3) == 0) {
            int r = wm * 64 + mt * 16 + (lid >> 2);
            atomicMax(&g_simmax[l * NQ + r],     enc_f(mx0));
            atomicMax(&g_simmax[l * NQ + r + 8], enc_f(mx1));
        }
    }
}

// ---------------- launch ----------------
extern "C" void kernel_launch(void* const* d_in, const int* in_sizes, int n_in,
                              void* d_out, int out_size) {
    const float* q = (const float*)d_in[0];
    const float* g = (const float*)d_in[1];
    if (n_in >= 2 && in_sizes[0] > in_sizes[1]) {
        const float* t = q; q = g; g = t;
    }
    cudaFuncSetAttribute(gemm_max_kernel,
                         cudaFuncAttributeMaxDynamicSharedMemorySize, SMEM_BYTES);

    init_kernel<<<1, NLAYERS * NQ>>>();
    prep_q_kernel<<<NLAYERS * NQ, 256>>>(q);
    gemm_max_kernel<<<dim3(NTILES, NLAYERS), 256, SMEM_BYTES>>>(g);
    finalize_kernel<<<1, NQ>>>((float*)d_out);
}

// round 11
// speedup vs baseline: 1.6398x; 1.1671x over previous
#include <cuda_runtime.h>
#include <cuda_fp16.h>
#include <cstdint>
#include <math.h>

#define NLAYERS 4
#define NQ      256
#define DIM     1024
#define MGAL    51200
#define KC      64                  // k-chunk (elems)
#define NCHUNK  (DIM / KC)          // 16
#define TILE_G  256                 // gallery rows per CTA
#define NTILES  (MGAL / TILE_G)     // 200

#define ROWB    144                 // 128B data + 16B pad (conflict-free ldmatrix)
#define ROWW    36                  // ROWB in words
#define ASTAGE  (NQ * ROWB)         // 36864
#define BSTAGE  (TILE_G * ROWB)     // 36864

#define OFF_MB0   0
#define OFF_MB1   16
#define OFF_INVN  64                // 256 floats
#define OFF_A     2048
#define OFF_B     (OFF_A + 2 * ASTAGE)       // 75776
#define SMEM_BYTES (OFF_B + 2 * BSTAGE)      // 149504

__device__ uint32_t g_qh[NLAYERS * NCHUNK * NQ * ROWW];  // f16 queries, chunk-major padded
__device__ unsigned int g_simmax[NLAYERS * NQ];          // monotone-encoded float max

// ---------------- helpers ----------------
__device__ __forceinline__ uint32_t smem_u32(const void* p) {
    uint32_t a;
    asm("{ .reg .u64 t; cvta.to.shared.u64 t, %1; cvt.u32.u64 %0, t; }" : "=r"(a) : "l"(p));
    return a;
}
__device__ __forceinline__ unsigned enc_f(float f) {
    unsigned u = __float_as_uint(f);
    return (u & 0x80000000u) ? ~u : (u | 0x80000000u);
}
__device__ __forceinline__ float dec_f(unsigned u) {
    return __uint_as_float((u & 0x80000000u) ? (u & 0x7fffffffu) : ~u);
}
// f16 x f16 -> f16 accumulate (D=C chain), m16n8k16
__device__ __forceinline__ void mma_h(uint32_t* d, const uint32_t* a, uint32_t b0, uint32_t b1) {
    asm volatile(
        "mma.sync.aligned.m16n8k16.row.col.f16.f16.f16.f16 "
        "{%0,%1}, {%2,%3,%4,%5}, {%6,%7}, {%0,%1};"
        : "+r"(d[0]), "+r"(d[1])
        : "r"(a[0]), "r"(a[1]), "r"(a[2]), "r"(a[3]), "r"(b0), "r"(b1));
}
__device__ __forceinline__ void ldmx4(uint32_t* r, uint32_t addr) {
    asm volatile("ldmatrix.sync.aligned.m8n8.x4.shared.b16 {%0,%1,%2,%3}, [%4];"
                 : "=r"(r[0]), "=r"(r[1]), "=r"(r[2]), "=r"(r[3]) : "r"(addr));
}
__device__ __forceinline__ void mbar_init(uint32_t addr, uint32_t cnt) {
    asm volatile("mbarrier.init.shared.b64 [%0], %1;" :: "r"(addr), "r"(cnt) : "memory");
}
__device__ __forceinline__ void mbar_expect_tx(uint32_t addr, uint32_t bytes) {
    asm volatile("mbarrier.arrive.expect_tx.shared.b64 _, [%0], %1;"
                 :: "r"(addr), "r"(bytes) : "memory");
}
__device__ __forceinline__ void mbar_wait(uint32_t addr, uint32_t parity) {
    asm volatile(
        "{\n\t.reg .pred P;\n"
        "W_%=:\n\t"
        "mbarrier.try_wait.parity.shared.b64 P, [%0], %1;\n\t"
        "@!P bra W_%=;\n\t}"
        :: "r"(addr), "r"(parity) : "memory");
}
__device__ __forceinline__ void bulk_cp(uint32_t dst, const void* src, uint32_t bytes, uint32_t mbar) {
    asm volatile(
        "cp.async.bulk.shared::cluster.global.mbarrier::complete_tx::bytes [%0], [%1], %2, [%3];"
        :: "r"(dst), "l"(src), "r"(bytes), "r"(mbar) : "memory");
}

// ---------------- small kernels ----------------
__global__ void init_kernel() {
    int i = blockIdx.x * blockDim.x + threadIdx.x;
    if (i < NLAYERS * NQ) g_simmax[i] = 0x007FFFFFu;  // enc(-inf)
}

// normalize queries -> f16, write chunk-major padded layout.
__global__ void prep_q_kernel(const float* __restrict__ q) {
    int row = blockIdx.x;                      // l*NQ + n
    int l = row >> 8, n = row & 255;
    const float4 f = reinterpret_cast<const float4*>(q + (size_t)row * DIM)[threadIdx.x];
    __shared__ float red[8];
    float ss = f.x*f.x + f.y*f.y + f.z*f.z + f.w*f.w;
    #pragma unroll
    for (int o = 16; o; o >>= 1) ss += __shfl_xor_sync(~0u, ss, o);
    if ((threadIdx.x & 31) == 0) red[threadIdx.x >> 5] = ss;
    __syncthreads();
    if (threadIdx.x < 8) {
        float s = red[threadIdx.x];
        #pragma unroll
        for (int o = 4; o; o >>= 1) s += __shfl_xor_sync(0xffu, s, o);
        if (threadIdx.x == 0) red[0] = s;
    }
    __syncthreads();
    float inv = 1.0f / fmaxf(sqrtf(red[0]), 1e-8f);
    int c = threadIdx.x >> 4;                  // chunk index
    int w = (threadIdx.x & 15) * 2;            // word offset within row-chunk
    uint32_t* dst = g_qh + ((size_t)(l * NCHUNK + c) * NQ + n) * ROWW + w;
    __half2 h0 = __floats2half2_rn(f.x * inv, f.y * inv);
    __half2 h1 = __floats2half2_rn(f.z * inv, f.w * inv);
    dst[0] = *reinterpret_cast<uint32_t*>(&h0);
    dst[1] = *reinterpret_cast<uint32_t*>(&h1);
}

__global__ void finalize_kernel(float* __restrict__ out) {
    int n = threadIdx.x;
    float s = 0.0f;
    #pragma unroll
    for (int l = 0; l < NLAYERS; l++) s += dec_f(g_simmax[l * NQ + n]);
    out[n] = 1.0f - s * (1.0f / NLAYERS);
}

// ---------------- main f16 GEMM + max kernel ----------------
__global__ __launch_bounds__(256, 1)
void gemm_max_kernel(const float* __restrict__ gal) {
    extern __shared__ char smem[];
    const uint32_t sb = smem_u32(smem);
    const int tid = threadIdx.x, wid = tid >> 5, lid = tid & 31;
    const int l  = blockIdx.y;
    const int g0 = blockIdx.x * TILE_G;
    const float* gB = gal + ((size_t)l * MGAL + g0) * DIM;
    const uint32_t* gAbase = g_qh + (size_t)l * NCHUNK * NQ * ROWW;

    float* invn = reinterpret_cast<float*>(smem + OFF_INVN);
    const int wm = wid >> 1, wn = wid & 1;       // warp tile: 64 q x 128 g
    const int rsel = lid & 15, usel = lid >> 4;

    // h2 accumulators: [mt 0..3][nt 0..15][2]
    uint32_t acc[4][16][2];
    #pragma unroll
    for (int mt = 0; mt < 4; mt++)
        #pragma unroll
        for (int nt = 0; nt < 16; nt++) { acc[mt][nt][0] = 0u; acc[mt][nt][1] = 0u; }

    // mbarrier init + prologue bulk A loads for chunks 0,1
    if (tid == 0) { mbar_init(sb + OFF_MB0, 1); mbar_init(sb + OFF_MB1, 1); }
    __syncthreads();
    if (tid == 0) {
        mbar_expect_tx(sb + OFF_MB0, ASTAGE);
        bulk_cp(sb + OFF_A, gAbase + 0 * NQ * ROWW, ASTAGE, sb + OFF_MB0);
        mbar_expect_tx(sb + OFF_MB1, ASTAGE);
        bulk_cp(sb + OFF_A + ASTAGE, gAbase + 1 * (size_t)NQ * ROWW, ASTAGE, sb + OFF_MB1);
    }

    // B prologue: thread t owns gallery row t; load chunk 0 (16 float4)
    float4 pb[16];
    {
        const float* src = gB + (size_t)tid * DIM;
        #pragma unroll
        for (int i = 0; i < 16; i++) pb[i] = *reinterpret_cast<const float4*>(src + i * 4);
    }
    float ss = 0.0f;

    for (int c = 0; c < NCHUNK; c++) {
        // ---- convert + store B chunk c (fp32 -> f16), accumulate row sumsq ----
        {
            const uint32_t dst = sb + OFF_B + (uint32_t)(c & 1) * BSTAGE + (uint32_t)(tid * ROWB);
            #pragma unroll
            for (int h = 0; h < 2; h++) {
                uint32_t w[16];
                #pragma unroll
                for (int i = 0; i < 8; i++) {
                    float4 f = pb[h * 8 + i];
                    ss = fmaf(f.x, f.x, fmaf(f.y, f.y, fmaf(f.z, f.z, fmaf(f.w, f.w, ss))));
                    __half2 h0 = __floats2half2_rn(f.x, f.y);
                    __half2 h1 = __floats2half2_rn(f.z, f.w);
                    w[i * 2]     = *reinterpret_cast<uint32_t*>(&h0);
                    w[i * 2 + 1] = *reinterpret_cast<uint32_t*>(&h1);
                }
                #pragma unroll
                for (int s4 = 0; s4 < 4; s4++)
                    asm volatile("st.shared.v4.b32 [%0], {%1, %2, %3, %4};"
                                 :: "r"(dst + (uint32_t)(h * 64 + s4 * 16)),
                                    "r"(w[s4*4]), "r"(w[s4*4+1]), "r"(w[s4*4+2]), "r"(w[s4*4+3])
                                 : "memory");
            }
        }
        // ---- prefetch next B chunk into regs ----
        if (c < NCHUNK - 1) {
            const float* src = gB + (size_t)tid * DIM + (c + 1) * KC;
            #pragma unroll
            for (int i = 0; i < 16; i++) pb[i] = *reinterpret_cast<const float4*>(src + i * 4);
        }
        // ---- wait A chunk c (bulk complete) ----
        mbar_wait(sb + ((c & 1) ? OFF_MB1 : OFF_MB0), (unsigned)((c >> 1) & 1));
        __syncthreads();

        // ---- compute: 4 k16-steps, warp tile 64q x 128g ----
        const uint32_t aBase = sb + OFF_A + (uint32_t)(c & 1) * ASTAGE;
        const uint32_t bBase = sb + OFF_B + (uint32_t)(c & 1) * BSTAGE;
        #pragma unroll
        for (int ks = 0; ks < 4; ks++) {
            uint32_t afr[4][4], bfr[8][4];
            #pragma unroll
            for (int mt = 0; mt < 4; mt++)
                ldmx4(afr[mt], aBase + (uint32_t)((wm * 64 + mt * 16 + rsel) * ROWB + ks * 32 + usel * 16));
            #pragma unroll
            for (int gb = 0; gb < 8; gb++)
                ldmx4(bfr[gb], bBase + (uint32_t)((wn * 128 + gb * 16 + rsel) * ROWB + ks * 32 + usel * 16));
            #pragma unroll
            for (int mt = 0; mt < 4; mt++)
                #pragma unroll
                for (int gb = 0; gb < 8; gb++) {
                    mma_h(acc[mt][2 * gb],     afr[mt], bfr[gb][0], bfr[gb][2]);
                    mma_h(acc[mt][2 * gb + 1], afr[mt], bfr[gb][1], bfr[gb][3]);
                }
        }
        __syncthreads();

        // ---- issue bulk A for chunk c+2 into freed stage ----
        if (tid == 0 && c + 2 < NCHUNK) {
            uint32_t mb = sb + ((c & 1) ? OFF_MB1 : OFF_MB0);
            mbar_expect_tx(mb, ASTAGE);
            bulk_cp(sb + OFF_A + (uint32_t)(c & 1) * ASTAGE,
                    gAbase + (size_t)(c + 2) * NQ * ROWW, ASTAGE, mb);
        }
    }

    // ---- gallery inverse norms (thread t owns row t) ----
    invn[tid] = 1.0f / fmaxf(sqrtf(ss), 1e-8f);
    __syncthreads();

    // ---- epilogue: unpack f16 acc, scale, per-query max, global atomicMax ----
    #pragma unroll
    for (int mt = 0; mt < 4; mt++) {
        float mx0 = -INFINITY, mx1 = -INFINITY;   // rows r0, r0+8
        #pragma unroll
        for (int nt = 0; nt < 16; nt++) {
            int colb = wn * 128 + nt * 8 + (lid & 3) * 2;
            float i0 = invn[colb], i1 = invn[colb + 1];
            __half2 h0 = *reinterpret_cast<__half2*>(&acc[mt][nt][0]);
            __half2 h1 = *reinterpret_cast<__half2*>(&acc[mt][nt][1]);
            mx0 = fmaxf(mx0, fmaxf(__low2float(h0) * i0, __high2float(h0) * i1));
            mx1 = fmaxf(mx1, fmaxf(__low2float(h1) * i0, __high2float(h1) * i1));
        }
        #pragma unroll
        for (int o = 1; o <= 2; o <<= 1) {
            mx0 = fmaxf(mx0, __shfl_xor_sync(~0u, mx0, o));
            mx1 = fmaxf(mx1, __shfl_xor_sync(~0u, mx1, o));
        }
        if ((lid & 3) == 0) {
            int r = wm * 64 + mt * 16 + (lid >> 2);
            atomicMax(&g_simmax[l * NQ + r],     enc_f(mx0));
            atomicMax(&g_simmax[l * NQ + r + 8], enc_f(mx1));
        }
    }
}

// ---------------- launch ----------------
extern "C" void kernel_launch(void* const* d_in, const int* in_sizes, int n_in,
                              void* d_out, int out_size) {
    const float* q = (const float*)d_in[0];
    const float* g = (const float*)d_in[1];
    if (n_in >= 2 && in_sizes[0] > in_sizes[1]) {
        const float* t = q; q = g; g = t;
    }
    cudaFuncSetAttribute(gemm_max_kernel,
                         cudaFuncAttributeMaxDynamicSharedMemorySize, SMEM_BYTES);

    init_kernel<<<1, NLAYERS * NQ>>>();
    prep_q_kernel<<<NLAYERS * NQ, 256>>>(q);
    gemm_max_kernel<<<dim3(NTILES, NLAYERS), 256, SMEM_BYTES>>>(g);
    finalize_kernel<<<1, NQ>>>((float*)d_out);
}